// round 1
// baseline (speedup 1.0000x reference)
#include <cuda_runtime.h>
#include <math.h>

#define N_NODES 100000
#define N_EDGES 1600000
#define VOCAB   2048
#define DIM     64
#define N_MASK  10000
#define M_PAD   10048   // N_MASK padded to 64-row GEMM tiles

// ---------------- scratch (device globals: allocation-free) ----------------
__device__ int   g_is64;
__device__ int   g_deg[N_NODES];
__device__ int   g_rowptr[N_NODES + 1];
__device__ int   g_cursor[N_NODES];
__device__ int   g_col[N_EDGES];
__device__ float g_h0[N_NODES * DIM];
__device__ float g_m1[N_NODES * DIM];
__device__ float g_h1[N_NODES * DIM];
__device__ float g_x2[M_PAD * 128];          // [mean2 | h1[mask]] rows; padded rows stay 0
__device__ float g_logits[N_MASK * 2048];

// ---------------- dtype detection (int32 vs int64 input indices) -----------
// Values are < 2^31 and non-negative. If stored little-endian int64, every odd
// 32-bit word is 0. For int32 data the odd words are random values in
// [0, N_NODES) -> probability all 32 are zero ~ 1e-160.
__global__ void detect_kernel(const void* edge) {
    const int* w = (const int*)edge;
    int lane = threadIdx.x;
    int v = w[2 * lane + 1];
    unsigned nz = __ballot_sync(0xffffffffu, v != 0);
    if (lane == 0) g_is64 = (nz == 0u) ? 1 : 0;
}

__device__ __forceinline__ int ld_idx(const void* p, long i, int is64) {
    return is64 ? (int)((const long long*)p)[i] : ((const int*)p)[i];
}

// ---------------- CSR build -------------------------------------------------
__global__ void zero_kernel() {
    int i = blockIdx.x * blockDim.x + threadIdx.x;
    if (i < N_NODES) { g_deg[i] = 0; g_cursor[i] = 0; }
}

__global__ void hist_kernel(const void* edge) {
    int is64 = g_is64;
    for (long e = blockIdx.x * (long)blockDim.x + threadIdx.x; e < N_EDGES;
         e += (long)gridDim.x * blockDim.x) {
        int d = ld_idx(edge, N_EDGES + e, is64);
        atomicAdd(&g_deg[d], 1);
    }
}

// single-block exclusive scan of g_deg -> g_rowptr
__global__ void scan_kernel() {
    __shared__ int s[1024];
    int t = threadIdx.x;
    const int CH = (N_NODES + 1023) / 1024;  // 98
    int lo = t * CH, hi = min(lo + CH, N_NODES);
    if (lo > N_NODES) lo = N_NODES;
    if (hi < lo) hi = lo;
    int sum = 0;
    for (int i = lo; i < hi; i++) sum += g_deg[i];
    s[t] = sum;
    __syncthreads();
    for (int off = 1; off < 1024; off <<= 1) {
        int v = (t >= off) ? s[t - off] : 0;
        __syncthreads();
        s[t] += v;
        __syncthreads();
    }
    int run = s[t] - sum;  // exclusive prefix for this chunk
    for (int i = lo; i < hi; i++) { g_rowptr[i] = run; run += g_deg[i]; }
    if (t == 1023) g_rowptr[N_NODES] = s[1023];
}

__global__ void scatter_kernel(const void* edge) {
    int is64 = g_is64;
    for (long e = blockIdx.x * (long)blockDim.x + threadIdx.x; e < N_EDGES;
         e += (long)gridDim.x * blockDim.x) {
        int s = ld_idx(edge, e, is64);
        int d = ld_idx(edge, N_EDGES + e, is64);
        int pos = g_rowptr[d] + atomicAdd(&g_cursor[d], 1);
        g_col[pos] = s;
    }
}

// ---------------- h0 = emb[x] ----------------------------------------------
__global__ void gather_kernel(const void* x, const float* emb) {
    int is64 = g_is64;
    int tid = blockIdx.x * blockDim.x + threadIdx.x;
    if (tid >= N_NODES * 16) return;
    int n = tid >> 4, j = tid & 15;
    int tok = ld_idx(x, n, is64);
    ((float4*)g_h0)[tid] = ((const float4*)emb)[tok * 16 + j];
}

// ---------------- SpMM mean, layer 1 (all nodes) ----------------------------
__global__ void spmm1_kernel() {
    int wid = (blockIdx.x * blockDim.x + threadIdx.x) >> 5;
    int lane = threadIdx.x & 31;
    if (wid >= N_NODES) return;
    int start = g_rowptr[wid], end = g_rowptr[wid + 1];
    float2 acc = make_float2(0.f, 0.f);
    const float2* h = (const float2*)g_h0;
    for (int p = start; p < end; p++) {
        int s = g_col[p];
        float2 v = h[(long)s * 32 + lane];
        acc.x += v.x; acc.y += v.y;
    }
    float inv = 1.0f / fmaxf((float)(end - start), 1.0f);
    ((float2*)g_m1)[(long)wid * 32 + lane] = make_float2(acc.x * inv, acc.y * inv);
}

// ---------------- dense layer 1: h1 = relu(m1@Wl + b + h0@Wr) ----------------
__global__ void dense1_kernel(const float* Wl, const float* bl, const float* Wr) {
    __shared__ float4 sP[2048];  // packed {Wl[k][l], Wl[k][l+32], Wr[k][l], Wr[k][l+32]}
    __shared__ float sb[64];
    int tid = threadIdx.x;
    for (int idx = tid; idx < 2048; idx += blockDim.x) {
        int k = idx >> 5, ln = idx & 31;
        sP[idx] = make_float4(Wl[k * 64 + ln], Wl[k * 64 + ln + 32],
                              Wr[k * 64 + ln], Wr[k * 64 + ln + 32]);
    }
    if (tid < 64) sb[tid] = bl[tid];
    __syncthreads();

    int lane = tid & 31;
    int warp = (blockIdx.x * blockDim.x + tid) >> 5;
    int nwarps = (gridDim.x * blockDim.x) >> 5;
    for (int n = warp; n < N_NODES; n += nwarps) {
        long base = (long)n * 64;
        float mlo = g_m1[base + lane], mhi = g_m1[base + 32 + lane];
        float hlo = g_h0[base + lane], hhi = g_h0[base + 32 + lane];
        float a0 = sb[lane], a1 = sb[lane + 32];
#pragma unroll
        for (int k = 0; k < 32; k++) {
            float mk = __shfl_sync(0xffffffffu, mlo, k);
            float hk = __shfl_sync(0xffffffffu, hlo, k);
            float4 p = sP[k * 32 + lane];
            a0 += mk * p.x + hk * p.z;
            a1 += mk * p.y + hk * p.w;
        }
#pragma unroll
        for (int k = 0; k < 32; k++) {
            float mk = __shfl_sync(0xffffffffu, mhi, k);
            float hk = __shfl_sync(0xffffffffu, hhi, k);
            float4 p = sP[(k + 32) * 32 + lane];
            a0 += mk * p.x + hk * p.z;
            a1 += mk * p.y + hk * p.w;
        }
        g_h1[base + lane]      = fmaxf(a0, 0.f);
        g_h1[base + 32 + lane] = fmaxf(a1, 0.f);
    }
}

// ---------------- SpMM mean, layer 2 (masked nodes only) --------------------
// builds x2[i] = [ mean_{src->n} h1[src] (64) | h1[n] (64) ]
__global__ void spmm2_kernel(const void* mask) {
    int is64 = g_is64;
    int wid = (blockIdx.x * blockDim.x + threadIdx.x) >> 5;
    int lane = threadIdx.x & 31;
    if (wid >= N_MASK) return;
    int n = ld_idx(mask, wid, is64);
    int start = g_rowptr[n], end = g_rowptr[n + 1];
    float2 acc = make_float2(0.f, 0.f);
    const float2* h = (const float2*)g_h1;
    for (int p = start; p < end; p++) {
        int s = g_col[p];
        float2 v = h[(long)s * 32 + lane];
        acc.x += v.x; acc.y += v.y;
    }
    float inv = 1.0f / fmaxf((float)(end - start), 1.0f);
    float2* x2 = (float2*)g_x2;
    x2[(long)wid * 64 + lane]      = make_float2(acc.x * inv, acc.y * inv);
    x2[(long)wid * 64 + 32 + lane] = h[(long)n * 32 + lane];
}

// ---------------- GEMM2: logits = x2 @ [W_l2; W_r2] + b_l2 ------------------
// C[10000,2048] = A[10048,128] * B[128,2048]; 64x64 tiles, 4x4 microtile.
__global__ void gemm2_kernel(const float* Wl2, const float* bl2, const float* Wr2) {
    __shared__ float As[128][64];  // transposed A tile: As[k][m]
    __shared__ float Bs[16][64];
    int tid = threadIdx.x;
    int tx = tid & 15, ty = tid >> 4;
    int rowBase = blockIdx.x * 64;
    int colBase = blockIdx.y * 64;

    // load A tile transposed: lanes vary m (row) -> conflict-free STS
#pragma unroll
    for (int j = 0; j < 8; j++) {
        int idx = tid + j * 256;
        int il = idx & 63;
        int k0 = (idx >> 6) << 2;
        float4 v = *(const float4*)&g_x2[(long)(rowBase + il) * 128 + k0];
        As[k0 + 0][il] = v.x; As[k0 + 1][il] = v.y;
        As[k0 + 2][il] = v.z; As[k0 + 3][il] = v.w;
    }

    float acc[4][4] = {};
    for (int kc = 0; kc < 8; kc++) {
        __syncthreads();
        {   // load 16x64 B chunk (from W_l2 rows 0..63, then W_r2 rows 0..63)
            int r = tid >> 4;
            int c = (tid & 15) * 4;
            int kg = kc * 16 + r;
            const float* W = (kg < 64) ? Wl2 : Wr2;
            int krow = (kg < 64) ? kg : kg - 64;
            float4 v = *(const float4*)&W[(long)krow * 2048 + colBase + c];
            *(float4*)&Bs[r][c] = v;
        }
        __syncthreads();
#pragma unroll
        for (int k = 0; k < 16; k++) {
            float4 a = *(const float4*)&As[kc * 16 + k][ty << 2];
            float4 b = *(const float4*)&Bs[k][tx << 2];
            acc[0][0] += a.x * b.x; acc[0][1] += a.x * b.y; acc[0][2] += a.x * b.z; acc[0][3] += a.x * b.w;
            acc[1][0] += a.y * b.x; acc[1][1] += a.y * b.y; acc[1][2] += a.y * b.z; acc[1][3] += a.y * b.w;
            acc[2][0] += a.z * b.x; acc[2][1] += a.z * b.y; acc[2][2] += a.z * b.z; acc[2][3] += a.z * b.w;
            acc[3][0] += a.w * b.x; acc[3][1] += a.w * b.y; acc[3][2] += a.w * b.z; acc[3][3] += a.w * b.w;
        }
    }

    float4 bv = *(const float4*)&bl2[colBase + (tx << 2)];
#pragma unroll
    for (int ii = 0; ii < 4; ii++) {
        int i = rowBase + (ty << 2) + ii;
        if (i < N_MASK) {
            float4 o = make_float4(acc[ii][0] + bv.x, acc[ii][1] + bv.y,
                                   acc[ii][2] + bv.z, acc[ii][3] + bv.w);
            *(float4*)&g_logits[(long)i * 2048 + colBase + (tx << 2)] = o;
        }
    }
}

// ---------------- row-wise log_softmax --------------------------------------
__global__ void softmax_kernel(float* out) {
    __shared__ float sred[256];
    int r = blockIdx.x;
    int t = threadIdx.x;
    const float4* L = (const float4*)&g_logits[(long)r * 2048];
    float4 v0 = L[t], v1 = L[t + 256];

    float mx = fmaxf(fmaxf(fmaxf(v0.x, v0.y), fmaxf(v0.z, v0.w)),
                     fmaxf(fmaxf(v1.x, v1.y), fmaxf(v1.z, v1.w)));
    sred[t] = mx; __syncthreads();
    for (int s = 128; s > 0; s >>= 1) {
        if (t < s) sred[t] = fmaxf(sred[t], sred[t + s]);
        __syncthreads();
    }
    mx = sred[0];
    __syncthreads();

    float sum = expf(v0.x - mx) + expf(v0.y - mx) + expf(v0.z - mx) + expf(v0.w - mx)
              + expf(v1.x - mx) + expf(v1.y - mx) + expf(v1.z - mx) + expf(v1.w - mx);
    sred[t] = sum; __syncthreads();
    for (int s = 128; s > 0; s >>= 1) {
        if (t < s) sred[t] += sred[t + s];
        __syncthreads();
    }
    float shift = mx + logf(sred[0]);

    float4* O = (float4*)&out[(long)r * 2048];
    O[t]       = make_float4(v0.x - shift, v0.y - shift, v0.z - shift, v0.w - shift);
    O[t + 256] = make_float4(v1.x - shift, v1.y - shift, v1.z - shift, v1.w - shift);
}

// ---------------- launch ----------------------------------------------------
extern "C" void kernel_launch(void* const* d_in, const int* in_sizes, int n_in,
                              void* d_out, int out_size) {
    const void*  x    = d_in[0];
    const void*  edge = d_in[1];
    const void*  mask = d_in[2];
    const float* emb  = (const float*)d_in[3];
    const float* Wl1  = (const float*)d_in[4];
    const float* bl1  = (const float*)d_in[5];
    const float* Wr1  = (const float*)d_in[6];
    const float* Wl2  = (const float*)d_in[7];
    const float* bl2  = (const float*)d_in[8];
    const float* Wr2  = (const float*)d_in[9];
    float* out = (float*)d_out;

    detect_kernel<<<1, 32>>>(edge);
    zero_kernel<<<(N_NODES + 255) / 256, 256>>>();
    hist_kernel<<<4096, 256>>>(edge);
    scan_kernel<<<1, 1024>>>();
    scatter_kernel<<<4096, 256>>>(edge);
    gather_kernel<<<(N_NODES * 16 + 255) / 256, 256>>>(x, emb);
    spmm1_kernel<<<(N_NODES * 32 + 255) / 256, 256>>>();
    dense1_kernel<<<1184, 256>>>(Wl1, bl1, Wr1);
    spmm2_kernel<<<(N_MASK * 32 + 255) / 256, 256>>>(mask);
    {
        dim3 grid((M_PAD) / 64, 2048 / 64);
        gemm2_kernel<<<grid, 256>>>(Wl2, bl2, Wr2);
    }
    softmax_kernel<<<N_MASK, 256>>>(out);
}

// round 3
// speedup vs baseline: 2.1100x; 2.1100x over previous
#include <cuda_runtime.h>
#include <cuda_bf16.h>
#include <math.h>
#include <stdint.h>

#define N_NODES 100000
#define N_EDGES 1600000
#define VOCAB   2048
#define DIM     64
#define N_MASK  10000
#define M_PAD   10112   // 79 * 128 (GEMM2 row tiles)

// ---------------- scratch (device globals: allocation-free) ----------------
__device__ int   g_is64;
__device__ int   g_deg[N_NODES];
__device__ int   g_rowptr[N_NODES + 1];
__device__ int   g_cursor[N_NODES];
__device__ int   g_col[N_EDGES];
__device__ int   g_bsum[100];
__device__ int   g_boff[100];
__device__ float g_h0[N_NODES * DIM];
__device__ float g_m1[N_NODES * DIM];
__device__ float g_h1[N_NODES * DIM];
__device__ float g_x2[M_PAD * 128];          // [mean2 | h1[mask]]; pad rows stay 0
__device__ float g_logits[N_MASK * 2048];

// ---------------- dtype detection (int32 vs int64 indices) -----------------
__global__ void detect_kernel(const void* edge) {
    const int* w = (const int*)edge;
    int lane = threadIdx.x;
    int v = w[2 * lane + 1];
    unsigned nz = __ballot_sync(0xffffffffu, v != 0);
    if (lane == 0) g_is64 = (nz == 0u) ? 1 : 0;
}

__device__ __forceinline__ int ld_idx(const void* p, long i, int is64) {
    return is64 ? (int)((const long long*)p)[i] : ((const int*)p)[i];
}

// ---------------- CSR build -------------------------------------------------
__global__ void zero_kernel() {
    int i = blockIdx.x * blockDim.x + threadIdx.x;
    if (i < N_NODES) { g_deg[i] = 0; g_cursor[i] = 0; }
}

__global__ void hist_kernel(const void* edge) {
    int is64 = g_is64;
    for (long e = blockIdx.x * (long)blockDim.x + threadIdx.x; e < N_EDGES;
         e += (long)gridDim.x * blockDim.x) {
        int d = ld_idx(edge, N_EDGES + e, is64);
        atomicAdd(&g_deg[d], 1);
    }
}

// 3-pass parallel exclusive scan of g_deg -> g_rowptr (chunks of 1000)
__global__ void scan1_kernel() {   // 100 blocks x 256
    __shared__ int s[256];
    int b = blockIdx.x, t = threadIdx.x;
    int sum = 0;
    if (t < 250) {
        int o = b * 1000 + t * 4;
        sum = g_deg[o] + g_deg[o + 1] + g_deg[o + 2] + g_deg[o + 3];
    }
    s[t] = sum; __syncthreads();
    for (int off = 128; off > 0; off >>= 1) {
        if (t < off) s[t] += s[t + off];
        __syncthreads();
    }
    if (t == 0) g_bsum[b] = s[0];
}

__global__ void scan2_kernel() {   // 1 block x 128
    __shared__ int s[128];
    int t = threadIdx.x;
    int v = (t < 100) ? g_bsum[t] : 0;
    s[t] = v; __syncthreads();
    for (int off = 1; off < 128; off <<= 1) {
        int x = (t >= off) ? s[t - off] : 0;
        __syncthreads();
        s[t] += x;
        __syncthreads();
    }
    if (t < 100) g_boff[t] = s[t] - v;
    if (t == 99) g_rowptr[N_NODES] = s[99];
}

__global__ void scan3_kernel() {   // 100 blocks x 256
    __shared__ int s[256];
    int b = blockIdx.x, t = threadIdx.x;
    int d0 = 0, d1 = 0, d2 = 0, d3 = 0, sum = 0;
    int o = b * 1000 + t * 4;
    if (t < 250) {
        d0 = g_deg[o]; d1 = g_deg[o + 1]; d2 = g_deg[o + 2]; d3 = g_deg[o + 3];
        sum = d0 + d1 + d2 + d3;
    }
    s[t] = sum; __syncthreads();
    for (int off = 1; off < 256; off <<= 1) {
        int x = (t >= off) ? s[t - off] : 0;
        __syncthreads();
        s[t] += x;
        __syncthreads();
    }
    if (t < 250) {
        int run = g_boff[b] + s[t] - sum;
        g_rowptr[o] = run; run += d0;
        g_rowptr[o + 1] = run; run += d1;
        g_rowptr[o + 2] = run; run += d2;
        g_rowptr[o + 3] = run;
    }
}

__global__ void scatter_kernel(const void* edge) {
    int is64 = g_is64;
    for (long e = blockIdx.x * (long)blockDim.x + threadIdx.x; e < N_EDGES;
         e += (long)gridDim.x * blockDim.x) {
        int s = ld_idx(edge, e, is64);
        int d = ld_idx(edge, N_EDGES + e, is64);
        int pos = g_rowptr[d] + atomicAdd(&g_cursor[d], 1);
        g_col[pos] = s;
    }
}

// ---------------- h0 = emb[x] ----------------------------------------------
__global__ void gather_kernel(const void* x, const float* emb) {
    int is64 = g_is64;
    int tid = blockIdx.x * blockDim.x + threadIdx.x;
    if (tid >= N_NODES * 16) return;
    int n = tid >> 4, j = tid & 15;
    int tok = ld_idx(x, n, is64);
    ((float4*)g_h0)[tid] = ((const float4*)emb)[tok * 16 + j];
}

// ---------------- SpMM mean, layer 1 (all nodes) ----------------------------
__global__ void spmm1_kernel() {
    int wid = (blockIdx.x * blockDim.x + threadIdx.x) >> 5;
    int lane = threadIdx.x & 31;
    if (wid >= N_NODES) return;
    int start = g_rowptr[wid], end = g_rowptr[wid + 1];
    float2 acc = make_float2(0.f, 0.f);
    const float2* h = (const float2*)g_h0;
    for (int p = start; p < end; p++) {
        int s = g_col[p];
        float2 v = h[(long)s * 32 + lane];
        acc.x += v.x; acc.y += v.y;
    }
    float inv = 1.0f / fmaxf((float)(end - start), 1.0f);
    ((float2*)g_m1)[(long)wid * 32 + lane] = make_float2(acc.x * inv, acc.y * inv);
}

// ---------------- dense layer 1 (tiled SIMT GEMM) ----------------------------
// h1[100000,64] = relu( [m1|h0][100000,128] @ [Wl1;Wr1][128,64] + b )
__global__ void __launch_bounds__(256) dense1_kernel(const float* Wl, const float* bl,
                                                     const float* Wr) {
    __shared__ float As[32][128];
    __shared__ float Bs[32][64];
    int tid = threadIdx.x;
    int tx = tid & 15, ty = tid >> 4;
    int rowBase = blockIdx.x * 128;
    float acc[8][4] = {};

    for (int kc = 0; kc < 4; kc++) {
        const float* src = (kc < 2) ? g_m1 : g_h0;
        int koff = (kc & 1) * 32;
#pragma unroll
        for (int it = 0; it < 4; it++) {
            int idx = tid + it * 256;
            int m = idx & 127;
            int k4 = (idx >> 7) << 2;
            int node = rowBase + m;
            float4 v = make_float4(0.f, 0.f, 0.f, 0.f);
            if (node < N_NODES) v = *(const float4*)&src[(long)node * 64 + koff + k4];
            As[k4][m] = v.x; As[k4 + 1][m] = v.y; As[k4 + 2][m] = v.z; As[k4 + 3][m] = v.w;
        }
#pragma unroll
        for (int it = 0; it < 2; it++) {
            int idx = tid + it * 256;
            int r = idx >> 4;
            int c = (idx & 15) * 4;
            int kg = kc * 32 + r;
            const float* W = (kg < 64) ? Wl : Wr;
            int kr = kg & 63;
            *(float4*)&Bs[r][c] = *(const float4*)&W[(long)kr * 64 + c];
        }
        __syncthreads();
#pragma unroll
        for (int k = 0; k < 32; k++) {
            float4 a0 = *(const float4*)&As[k][ty * 8];
            float4 a1 = *(const float4*)&As[k][ty * 8 + 4];
            float4 b = *(const float4*)&Bs[k][tx * 4];
            float av[8] = {a0.x, a0.y, a0.z, a0.w, a1.x, a1.y, a1.z, a1.w};
#pragma unroll
            for (int i = 0; i < 8; i++) {
                acc[i][0] += av[i] * b.x; acc[i][1] += av[i] * b.y;
                acc[i][2] += av[i] * b.z; acc[i][3] += av[i] * b.w;
            }
        }
        __syncthreads();
    }

    float4 bv = *(const float4*)&bl[tx * 4];
#pragma unroll
    for (int i = 0; i < 8; i++) {
        int row = rowBase + ty * 8 + i;
        if (row < N_NODES) {
            float4 o = make_float4(fmaxf(acc[i][0] + bv.x, 0.f), fmaxf(acc[i][1] + bv.y, 0.f),
                                   fmaxf(acc[i][2] + bv.z, 0.f), fmaxf(acc[i][3] + bv.w, 0.f));
            *(float4*)&g_h1[(long)row * 64 + tx * 4] = o;
        }
    }
}

// ---------------- SpMM mean, layer 2 (masked nodes only) --------------------
__global__ void spmm2_kernel(const void* mask) {
    int is64 = g_is64;
    int wid = (blockIdx.x * blockDim.x + threadIdx.x) >> 5;
    int lane = threadIdx.x & 31;
    if (wid >= N_MASK) return;
    int n = ld_idx(mask, wid, is64);
    int start = g_rowptr[n], end = g_rowptr[n + 1];
    float2 acc = make_float2(0.f, 0.f);
    const float2* h = (const float2*)g_h1;
    for (int p = start; p < end; p++) {
        int s = g_col[p];
        float2 v = h[(long)s * 32 + lane];
        acc.x += v.x; acc.y += v.y;
    }
    float inv = 1.0f / fmaxf((float)(end - start), 1.0f);
    float2* x2 = (float2*)g_x2;
    x2[(long)wid * 64 + lane]      = make_float2(acc.x * inv, acc.y * inv);
    x2[(long)wid * 64 + 32 + lane] = h[(long)n * 32 + lane];
}

// ================= GEMM2 on tensor cores (mma.sync bf16 split) ==============
// logits[10000,2048] = x2[10112,128] @ [Wl2;Wr2][128,2048] + b
// Markidis split: A=Ah+Al, B=Bh+Bl (bf16), D = AhBh + AhBl + AlBh, fp32 accum.
// CTA tile 128x128xK128, 8 warps (2x4), warp tile 64x32, mma.m16n8k16.

static __device__ __forceinline__ uint32_t pack_bf2(float a, float b) {
    __nv_bfloat162 t = __floats2bfloat162_rn(a, b);
    return reinterpret_cast<uint32_t&>(t);
}
static __device__ __forceinline__ void split8(const float* v, uint4& hi, uint4& lo) {
    float r[8];
#pragma unroll
    for (int i = 0; i < 8; i++)
        r[i] = v[i] - __bfloat162float(__float2bfloat16(v[i]));
    hi = make_uint4(pack_bf2(v[0], v[1]), pack_bf2(v[2], v[3]),
                    pack_bf2(v[4], v[5]), pack_bf2(v[6], v[7]));
    lo = make_uint4(pack_bf2(r[0], r[1]), pack_bf2(r[2], r[3]),
                    pack_bf2(r[4], r[5]), pack_bf2(r[6], r[7]));
}

#define MMA16816(d, a, b) \
    asm volatile( \
        "mma.sync.aligned.m16n8k16.row.col.f32.bf16.bf16.f32 " \
        "{%0,%1,%2,%3}, {%4,%5,%6,%7}, {%8,%9}, {%0,%1,%2,%3};" \
        : "+f"((d)[0]), "+f"((d)[1]), "+f"((d)[2]), "+f"((d)[3]) \
        : "r"((a)[0]), "r"((a)[1]), "r"((a)[2]), "r"((a)[3]), \
          "r"((b)[0]), "r"((b)[1]))

#define GSTR 136                           // bf16 per smem row (68 words: conflict-free)
#define GT_SMEM (4 * 128 * GSTR * 2)       // 4 tiles of [128][136] bf16 = 139264 B

__global__ void __launch_bounds__(256, 1) gemm2_mma(const float* __restrict__ Wl2,
                                                    const float* __restrict__ bl2,
                                                    const float* __restrict__ Wr2) {
    extern __shared__ __nv_bfloat16 sm[];
    __nv_bfloat16* AH = sm;
    __nv_bfloat16* AL = sm + 128 * GSTR;
    __nv_bfloat16* BH = sm + 2 * 128 * GSTR;
    __nv_bfloat16* BL = sm + 3 * 128 * GSTR;

    int tid = threadIdx.x;
    int lane = tid & 31, wid = tid >> 5;
    int rowBase = blockIdx.x * 128;
    int colBase = blockIdx.y * 128;

    // ---- stage A: 128 rows x 128 k (fp32 -> bf16 hi/lo), k-major ----
#pragma unroll
    for (int it = 0; it < 8; it++) {
        int p = tid + it * 256;          // 0..2047
        int m = p >> 4;                  // 0..127
        int koct = p & 15;               // 8 k's each
        const float* src = &g_x2[(long)(rowBase + m) * 128 + koct * 8];
        float4 v0 = *(const float4*)src;
        float4 v1 = *(const float4*)(src + 4);
        float v[8] = {v0.x, v0.y, v0.z, v0.w, v1.x, v1.y, v1.z, v1.w};
        uint4 hi, lo;
        split8(v, hi, lo);
        *(uint4*)&AH[m * GSTR + koct * 8] = hi;
        *(uint4*)&AL[m * GSTR + koct * 8] = lo;
    }
    // ---- stage B: [n][k] (k-major), from W rows (n contiguous -> coalesced) ----
#pragma unroll
    for (int it = 0; it < 8; it++) {
        int p = tid + it * 256;
        int n = p & 127;
        int koct = p >> 7;               // 0..15
        const float* W = (koct < 8) ? Wl2 : Wr2;
        int kr0 = (koct * 8) & 63;
        float v[8];
#pragma unroll
        for (int j = 0; j < 8; j++)
            v[j] = W[(long)(kr0 + j) * 2048 + colBase + n];
        uint4 hi, lo;
        split8(v, hi, lo);
        *(uint4*)&BH[n * GSTR + koct * 8] = hi;
        *(uint4*)&BL[n * GSTR + koct * 8] = lo;
    }
    __syncthreads();

    int tig = lane & 3, grp = lane >> 2;
    int wm = (wid >> 2) * 64;            // warp M offset (0 / 64)
    int wn = (wid & 3) * 32;             // warp N offset (0/32/64/96)

    float acc[4][4][4] = {};

#pragma unroll
    for (int ks = 0; ks < 8; ks++) {
        int kw = ks * 8 + tig;           // bf16-pair (word) index along k
        uint32_t aH[4][4], aL[4][4], bH[4][2], bL[4][2];
#pragma unroll
        for (int mt = 0; mt < 4; mt++) {
            const __nv_bfloat16* pH = &AH[(wm + mt * 16 + grp) * GSTR + kw * 2];
            const __nv_bfloat16* pL = &AL[(wm + mt * 16 + grp) * GSTR + kw * 2];
            aH[mt][0] = *(const uint32_t*)pH;
            aH[mt][1] = *(const uint32_t*)(pH + 8 * GSTR);
            aH[mt][2] = *(const uint32_t*)(pH + 8);
            aH[mt][3] = *(const uint32_t*)(pH + 8 * GSTR + 8);
            aL[mt][0] = *(const uint32_t*)pL;
            aL[mt][1] = *(const uint32_t*)(pL + 8 * GSTR);
            aL[mt][2] = *(const uint32_t*)(pL + 8);
            aL[mt][3] = *(const uint32_t*)(pL + 8 * GSTR + 8);
        }
#pragma unroll
        for (int nt = 0; nt < 4; nt++) {
            const __nv_bfloat16* pH = &BH[(wn + nt * 8 + grp) * GSTR + kw * 2];
            const __nv_bfloat16* pL = &BL[(wn + nt * 8 + grp) * GSTR + kw * 2];
            bH[nt][0] = *(const uint32_t*)pH;
            bH[nt][1] = *(const uint32_t*)(pH + 8);
            bL[nt][0] = *(const uint32_t*)pL;
            bL[nt][1] = *(const uint32_t*)(pL + 8);
        }
#pragma unroll
        for (int mt = 0; mt < 4; mt++)
#pragma unroll
            for (int nt = 0; nt < 4; nt++) {
                MMA16816(acc[mt][nt], aH[mt], bH[nt]);
                MMA16816(acc[mt][nt], aH[mt], bL[nt]);
                MMA16816(acc[mt][nt], aL[mt], bH[nt]);
            }
    }

    // ---- epilogue: add bias, store fp32 ----
#pragma unroll
    for (int mt = 0; mt < 4; mt++) {
#pragma unroll
        for (int nt = 0; nt < 4; nt++) {
            int row = rowBase + wm + mt * 16 + grp;
            int col = colBase + wn + nt * 8 + tig * 2;
            float2 bv = *(const float2*)&bl2[col];
            if (row < N_MASK) {
                float2 o = make_float2(acc[mt][nt][0] + bv.x, acc[mt][nt][1] + bv.y);
                *(float2*)&g_logits[(long)row * 2048 + col] = o;
            }
            if (row + 8 < N_MASK) {
                float2 o = make_float2(acc[mt][nt][2] + bv.x, acc[mt][nt][3] + bv.y);
                *(float2*)&g_logits[(long)(row + 8) * 2048 + col] = o;
            }
        }
    }
}

// ---------------- row-wise log_softmax --------------------------------------
__global__ void softmax_kernel(float* out) {
    __shared__ float sred[256];
    int r = blockIdx.x;
    int t = threadIdx.x;
    const float4* L = (const float4*)&g_logits[(long)r * 2048];
    float4 v0 = L[t], v1 = L[t + 256];

    float mx = fmaxf(fmaxf(fmaxf(v0.x, v0.y), fmaxf(v0.z, v0.w)),
                     fmaxf(fmaxf(v1.x, v1.y), fmaxf(v1.z, v1.w)));
    sred[t] = mx; __syncthreads();
    for (int s = 128; s > 0; s >>= 1) {
        if (t < s) sred[t] = fmaxf(sred[t], sred[t + s]);
        __syncthreads();
    }
    mx = sred[0];
    __syncthreads();

    float sum = expf(v0.x - mx) + expf(v0.y - mx) + expf(v0.z - mx) + expf(v0.w - mx)
              + expf(v1.x - mx) + expf(v1.y - mx) + expf(v1.z - mx) + expf(v1.w - mx);
    sred[t] = sum; __syncthreads();
    for (int s = 128; s > 0; s >>= 1) {
        if (t < s) sred[t] += sred[t + s];
        __syncthreads();
    }
    float shift = mx + logf(sred[0]);

    float4* O = (float4*)&out[(long)r * 2048];
    O[t]       = make_float4(v0.x - shift, v0.y - shift, v0.z - shift, v0.w - shift);
    O[t + 256] = make_float4(v1.x - shift, v1.y - shift, v1.z - shift, v1.w - shift);
}

// ---------------- launch ----------------------------------------------------
extern "C" void kernel_launch(void* const* d_in, const int* in_sizes, int n_in,
                              void* d_out, int out_size) {
    const void*  x    = d_in[0];
    const void*  edge = d_in[1];
    const void*  mask = d_in[2];
    const float* emb  = (const float*)d_in[3];
    const float* Wl1  = (const float*)d_in[4];
    const float* bl1  = (const float*)d_in[5];
    const float* Wr1  = (const float*)d_in[6];
    const float* Wl2  = (const float*)d_in[7];
    const float* bl2  = (const float*)d_in[8];
    const float* Wr2  = (const float*)d_in[9];
    float* out = (float*)d_out;

    cudaFuncSetAttribute(gemm2_mma, cudaFuncAttributeMaxDynamicSharedMemorySize, GT_SMEM);

    detect_kernel<<<1, 32>>>(edge);
    zero_kernel<<<(N_NODES + 255) / 256, 256>>>();
    hist_kernel<<<4096, 256>>>(edge);
    scan1_kernel<<<100, 256>>>();
    scan2_kernel<<<1, 128>>>();
    scan3_kernel<<<100, 256>>>();
    scatter_kernel<<<4096, 256>>>(edge);
    gather_kernel<<<(N_NODES * 16 + 255) / 256, 256>>>(x, emb);
    spmm1_kernel<<<(N_NODES * 32 + 255) / 256, 256>>>();
    dense1_kernel<<<(N_NODES + 127) / 128, 256>>>(Wl1, bl1, Wr1);
    spmm2_kernel<<<(N_MASK * 32 + 255) / 256, 256>>>(mask);
    {
        dim3 grid(M_PAD / 128, 2048 / 128);
        gemm2_mma<<<grid, 256, GT_SMEM>>>(Wl2, bl2, Wr2);
    }
    softmax_kernel<<<N_MASK, 256>>>(out);
}

// round 4
// speedup vs baseline: 2.3606x; 1.1188x over previous
#include <cuda_runtime.h>
#include <cuda_bf16.h>
#include <math.h>
#include <stdint.h>

#define N_NODES 100000
#define N_EDGES 1600000
#define VOCAB   2048
#define DIM     64
#define N_MASK  10000
#define M_PAD   10112   // 79 * 128 (GEMM2 row tiles)

// ---------------- scratch (device globals: allocation-free) ----------------
__device__ int   g_is64;
__device__ int   g_deg[N_NODES];
__device__ int   g_rowptr[N_NODES + 1];
__device__ int   g_cursor[N_NODES];
__device__ int   g_col[N_EDGES];
__device__ int   g_bsum[100];
__device__ int   g_boff[100];
__device__ float g_h0[N_NODES * DIM];
__device__ float g_m1[N_NODES * DIM];
__device__ float g_h1[N_NODES * DIM];
__device__ float g_x2[M_PAD * 128];          // [mean2 | h1[mask]]; pad rows stay 0
__device__ float g_logits[N_MASK * 2048];

// ---------------- dtype detection (int32 vs int64 indices) -----------------
__global__ void detect_kernel(const void* edge) {
    const int* w = (const int*)edge;
    int lane = threadIdx.x;
    int v = w[2 * lane + 1];
    unsigned nz = __ballot_sync(0xffffffffu, v != 0);
    if (lane == 0) g_is64 = (nz == 0u) ? 1 : 0;
}

__device__ __forceinline__ int ld_idx(const void* p, long i, int is64) {
    return is64 ? (int)((const long long*)p)[i] : ((const int*)p)[i];
}

// ---------------- CSR build -------------------------------------------------
__global__ void zero_kernel() {
    int i = blockIdx.x * blockDim.x + threadIdx.x;
    if (i < N_NODES) { g_deg[i] = 0; g_cursor[i] = 0; }
}

// 2 edges per thread, vectorized loads
__global__ void hist_kernel(const void* edge) {
    int is64 = g_is64;
    long t = blockIdx.x * (long)blockDim.x + threadIdx.x;
    long e = t * 2;
    if (e >= N_EDGES) return;
    int d0, d1;
    if (is64) {
        longlong2 v = *(const longlong2*)((const long long*)edge + N_EDGES + e);
        d0 = (int)v.x; d1 = (int)v.y;
    } else {
        int2 v = *(const int2*)((const int*)edge + N_EDGES + e);
        d0 = v.x; d1 = v.y;
    }
    atomicAdd(&g_deg[d0], 1);
    atomicAdd(&g_deg[d1], 1);
}

// 3-pass parallel exclusive scan of g_deg -> g_rowptr (chunks of 1000)
__global__ void scan1_kernel() {   // 100 blocks x 256
    __shared__ int s[256];
    int b = blockIdx.x, t = threadIdx.x;
    int sum = 0;
    if (t < 250) {
        int o = b * 1000 + t * 4;
        sum = g_deg[o] + g_deg[o + 1] + g_deg[o + 2] + g_deg[o + 3];
    }
    s[t] = sum; __syncthreads();
    for (int off = 128; off > 0; off >>= 1) {
        if (t < off) s[t] += s[t + off];
        __syncthreads();
    }
    if (t == 0) g_bsum[b] = s[0];
}

__global__ void scan2_kernel() {   // 1 block x 128
    __shared__ int s[128];
    int t = threadIdx.x;
    int v = (t < 100) ? g_bsum[t] : 0;
    s[t] = v; __syncthreads();
    for (int off = 1; off < 128; off <<= 1) {
        int x = (t >= off) ? s[t - off] : 0;
        __syncthreads();
        s[t] += x;
        __syncthreads();
    }
    if (t < 100) g_boff[t] = s[t] - v;
    if (t == 99) g_rowptr[N_NODES] = s[99];
}

__global__ void scan3_kernel() {   // 100 blocks x 256
    __shared__ int s[256];
    int b = blockIdx.x, t = threadIdx.x;
    int d0 = 0, d1 = 0, d2 = 0, d3 = 0, sum = 0;
    int o = b * 1000 + t * 4;
    if (t < 250) {
        d0 = g_deg[o]; d1 = g_deg[o + 1]; d2 = g_deg[o + 2]; d3 = g_deg[o + 3];
        sum = d0 + d1 + d2 + d3;
    }
    s[t] = sum; __syncthreads();
    for (int off = 1; off < 256; off <<= 1) {
        int x = (t >= off) ? s[t - off] : 0;
        __syncthreads();
        s[t] += x;
        __syncthreads();
    }
    if (t < 250) {
        int run = g_boff[b] + s[t] - sum;
        g_rowptr[o] = run; run += d0;
        g_rowptr[o + 1] = run; run += d1;
        g_rowptr[o + 2] = run; run += d2;
        g_rowptr[o + 3] = run;
    }
}

__global__ void scatter_kernel(const void* edge) {
    int is64 = g_is64;
    long t = blockIdx.x * (long)blockDim.x + threadIdx.x;
    long e = t * 2;
    if (e >= N_EDGES) return;
    int s0, s1, d0, d1;
    if (is64) {
        longlong2 sv = *(const longlong2*)((const long long*)edge + e);
        longlong2 dv = *(const longlong2*)((const long long*)edge + N_EDGES + e);
        s0 = (int)sv.x; s1 = (int)sv.y; d0 = (int)dv.x; d1 = (int)dv.y;
    } else {
        int2 sv = *(const int2*)((const int*)edge + e);
        int2 dv = *(const int2*)((const int*)edge + N_EDGES + e);
        s0 = sv.x; s1 = sv.y; d0 = dv.x; d1 = dv.y;
    }
    int p0 = g_rowptr[d0] + atomicAdd(&g_cursor[d0], 1);
    g_col[p0] = s0;
    int p1 = g_rowptr[d1] + atomicAdd(&g_cursor[d1], 1);
    g_col[p1] = s1;
}

// ---------------- h0 = emb[x] ----------------------------------------------
__global__ void gather_kernel(const void* x, const float* emb) {
    int is64 = g_is64;
    int tid = blockIdx.x * blockDim.x + threadIdx.x;
    if (tid >= N_NODES * 16) return;
    int n = tid >> 4, j = tid & 15;
    int tok = ld_idx(x, n, is64);
    ((float4*)g_h0)[tid] = ((const float4*)emb)[tok * 16 + j];
}

// ---------------- SpMM mean, layer 1 (all nodes) ----------------------------
// warp per node; half-warps process alternating edges, float4 gathers
__global__ void spmm1_kernel() {
    int wid = (blockIdx.x * blockDim.x + threadIdx.x) >> 5;
    int lane = threadIdx.x & 31;
    if (wid >= N_NODES) return;
    int half = lane >> 4, l16 = lane & 15;
    int start = g_rowptr[wid], end = g_rowptr[wid + 1];
    float4 acc = make_float4(0.f, 0.f, 0.f, 0.f);
    const float4* h = (const float4*)g_h0;
    for (int p = start + half; p < end; p += 2) {
        int s = g_col[p];
        float4 v = h[(long)s * 16 + l16];
        acc.x += v.x; acc.y += v.y; acc.z += v.z; acc.w += v.w;
    }
    acc.x += __shfl_down_sync(0xffffffffu, acc.x, 16);
    acc.y += __shfl_down_sync(0xffffffffu, acc.y, 16);
    acc.z += __shfl_down_sync(0xffffffffu, acc.z, 16);
    acc.w += __shfl_down_sync(0xffffffffu, acc.w, 16);
    if (half == 0) {
        float inv = 1.0f / fmaxf((float)(end - start), 1.0f);
        ((float4*)g_m1)[(long)wid * 16 + l16] =
            make_float4(acc.x * inv, acc.y * inv, acc.z * inv, acc.w * inv);
    }
}

// =============== bf16 mma.sync helpers (shared by dense1 & gemm2) ===========
static __device__ __forceinline__ uint32_t pack_bf2(float a, float b) {
    __nv_bfloat162 t = __floats2bfloat162_rn(a, b);
    return reinterpret_cast<uint32_t&>(t);
}
static __device__ __forceinline__ void split8(const float* v, uint4& hi, uint4& lo) {
    float r[8];
#pragma unroll
    for (int i = 0; i < 8; i++)
        r[i] = v[i] - __bfloat162float(__float2bfloat16(v[i]));
    hi = make_uint4(pack_bf2(v[0], v[1]), pack_bf2(v[2], v[3]),
                    pack_bf2(v[4], v[5]), pack_bf2(v[6], v[7]));
    lo = make_uint4(pack_bf2(r[0], r[1]), pack_bf2(r[2], r[3]),
                    pack_bf2(r[4], r[5]), pack_bf2(r[6], r[7]));
}

#define MMA16816(d, a, b) \
    asm volatile( \
        "mma.sync.aligned.m16n8k16.row.col.f32.bf16.bf16.f32 " \
        "{%0,%1,%2,%3}, {%4,%5,%6,%7}, {%8,%9}, {%0,%1,%2,%3};" \
        : "+f"((d)[0]), "+f"((d)[1]), "+f"((d)[2]), "+f"((d)[3]) \
        : "r"((a)[0]), "r"((a)[1]), "r"((a)[2]), "r"((a)[3]), \
          "r"((b)[0]), "r"((b)[1]))

#define GSTR 136                            // bf16 per smem row (conflict-free)
#define GT_SMEM (4 * 128 * GSTR * 2)        // gemm2: 139264 B
#define D1_SMEM ((128 + 64) * 2 * GSTR * 2) // dense1: 104448 B

// ---------------- dense layer 1 (tensor-core bf16 split) --------------------
// h1[100000,64] = relu( [m1|h0][100000,128] @ [Wl1;Wr1][128,64] + b )
__global__ void __launch_bounds__(256) dense1_mma(const float* __restrict__ Wl,
                                                  const float* __restrict__ bl,
                                                  const float* __restrict__ Wr) {
    extern __shared__ __nv_bfloat16 sm[];
    __nv_bfloat16* AH = sm;
    __nv_bfloat16* AL = sm + 128 * GSTR;
    __nv_bfloat16* BH = sm + 2 * 128 * GSTR;
    __nv_bfloat16* BL = sm + 2 * 128 * GSTR + 64 * GSTR;

    int tid = threadIdx.x;
    int lane = tid & 31, wid = tid >> 5;
    int rowBase = blockIdx.x * 128;

    // stage A: [m][k], k 0..63 from m1, 64..127 from h0
#pragma unroll
    for (int it = 0; it < 8; it++) {
        int p = tid + it * 256;
        int m = p >> 4, koct = p & 15;
        int node = rowBase + m;
        float v[8] = {0, 0, 0, 0, 0, 0, 0, 0};
        if (node < N_NODES) {
            const float* src = (koct < 8) ? &g_m1[(long)node * 64 + koct * 8]
                                          : &g_h0[(long)node * 64 + (koct - 8) * 8];
            float4 v0 = *(const float4*)src;
            float4 v1 = *(const float4*)(src + 4);
            v[0] = v0.x; v[1] = v0.y; v[2] = v0.z; v[3] = v0.w;
            v[4] = v1.x; v[5] = v1.y; v[6] = v1.z; v[7] = v1.w;
        }
        uint4 hi, lo;
        split8(v, hi, lo);
        *(uint4*)&AH[m * GSTR + koct * 8] = hi;
        *(uint4*)&AL[m * GSTR + koct * 8] = lo;
    }
    // stage B: [n][k], n=0..63; B[n][k] = W[k][n], k<64 Wl else Wr
#pragma unroll
    for (int it = 0; it < 4; it++) {
        int p = tid + it * 256;
        int n = p & 63, koct = p >> 6;
        const float* W = (koct < 8) ? Wl : Wr;
        int kr0 = (koct * 8) & 63;
        float v[8];
#pragma unroll
        for (int j = 0; j < 8; j++)
            v[j] = W[(long)(kr0 + j) * 64 + n];
        uint4 hi, lo;
        split8(v, hi, lo);
        *(uint4*)&BH[n * GSTR + koct * 8] = hi;
        *(uint4*)&BL[n * GSTR + koct * 8] = lo;
    }
    __syncthreads();

    int tig = lane & 3, grp = lane >> 2;
    int wm = (wid & 3) * 32;     // warp M offset
    int wn = (wid >> 2) * 32;    // warp N offset

    float acc[2][4][4] = {};

#pragma unroll
    for (int ks = 0; ks < 8; ks++) {
        int kw = ks * 8 + tig;
        uint32_t aH[2][4], aL[2][4], bH[4][2], bL[4][2];
#pragma unroll
        for (int mt = 0; mt < 2; mt++) {
            const __nv_bfloat16* pH = &AH[(wm + mt * 16 + grp) * GSTR + kw * 2];
            const __nv_bfloat16* pL = &AL[(wm + mt * 16 + grp) * GSTR + kw * 2];
            aH[mt][0] = *(const uint32_t*)pH;
            aH[mt][1] = *(const uint32_t*)(pH + 8 * GSTR);
            aH[mt][2] = *(const uint32_t*)(pH + 8);
            aH[mt][3] = *(const uint32_t*)(pH + 8 * GSTR + 8);
            aL[mt][0] = *(const uint32_t*)pL;
            aL[mt][1] = *(const uint32_t*)(pL + 8 * GSTR);
            aL[mt][2] = *(const uint32_t*)(pL + 8);
            aL[mt][3] = *(const uint32_t*)(pL + 8 * GSTR + 8);
        }
#pragma unroll
        for (int nt = 0; nt < 4; nt++) {
            const __nv_bfloat16* pH = &BH[(wn + nt * 8 + grp) * GSTR + kw * 2];
            const __nv_bfloat16* pL = &BL[(wn + nt * 8 + grp) * GSTR + kw * 2];
            bH[nt][0] = *(const uint32_t*)pH;
            bH[nt][1] = *(const uint32_t*)(pH + 8);
            bL[nt][0] = *(const uint32_t*)pL;
            bL[nt][1] = *(const uint32_t*)(pL + 8);
        }
#pragma unroll
        for (int mt = 0; mt < 2; mt++)
#pragma unroll
            for (int nt = 0; nt < 4; nt++) {
                MMA16816(acc[mt][nt], aH[mt], bH[nt]);
                MMA16816(acc[mt][nt], aH[mt], bL[nt]);
                MMA16816(acc[mt][nt], aL[mt], bH[nt]);
            }
    }

    // epilogue: relu(acc + bias) -> g_h1
#pragma unroll
    for (int mt = 0; mt < 2; mt++) {
#pragma unroll
        for (int nt = 0; nt < 4; nt++) {
            int row = rowBase + wm + mt * 16 + grp;
            int col = wn + nt * 8 + tig * 2;
            float2 bv = *(const float2*)&bl[col];
            if (row < N_NODES) {
                float2 o = make_float2(fmaxf(acc[mt][nt][0] + bv.x, 0.f),
                                       fmaxf(acc[mt][nt][1] + bv.y, 0.f));
                *(float2*)&g_h1[(long)row * 64 + col] = o;
            }
            if (row + 8 < N_NODES) {
                float2 o = make_float2(fmaxf(acc[mt][nt][2] + bv.x, 0.f),
                                       fmaxf(acc[mt][nt][3] + bv.y, 0.f));
                *(float2*)&g_h1[(long)(row + 8) * 64 + col] = o;
            }
        }
    }
}

// ---------------- SpMM mean, layer 2 (masked nodes only) --------------------
__global__ void spmm2_kernel(const void* mask) {
    int is64 = g_is64;
    int wid = (blockIdx.x * blockDim.x + threadIdx.x) >> 5;
    int lane = threadIdx.x & 31;
    if (wid >= N_MASK) return;
    int half = lane >> 4, l16 = lane & 15;
    int n = ld_idx(mask, wid, is64);
    int start = g_rowptr[n], end = g_rowptr[n + 1];
    float4 acc = make_float4(0.f, 0.f, 0.f, 0.f);
    const float4* h = (const float4*)g_h1;
    for (int p = start + half; p < end; p += 2) {
        int s = g_col[p];
        float4 v = h[(long)s * 16 + l16];
        acc.x += v.x; acc.y += v.y; acc.z += v.z; acc.w += v.w;
    }
    acc.x += __shfl_down_sync(0xffffffffu, acc.x, 16);
    acc.y += __shfl_down_sync(0xffffffffu, acc.y, 16);
    acc.z += __shfl_down_sync(0xffffffffu, acc.z, 16);
    acc.w += __shfl_down_sync(0xffffffffu, acc.w, 16);
    float4* x2 = (float4*)g_x2;
    if (half == 0) {
        float inv = 1.0f / fmaxf((float)(end - start), 1.0f);
        x2[(long)wid * 32 + l16] =
            make_float4(acc.x * inv, acc.y * inv, acc.z * inv, acc.w * inv);
    } else {
        x2[(long)wid * 32 + 16 + l16] = h[(long)n * 16 + l16];
    }
}

// ================= GEMM2 on tensor cores (mma.sync bf16 split) ==============
// logits[10000,2048] = x2[10112,128] @ [Wl2;Wr2][128,2048] + b
__global__ void __launch_bounds__(256, 1) gemm2_mma(const float* __restrict__ Wl2,
                                                    const float* __restrict__ bl2,
                                                    const float* __restrict__ Wr2) {
    extern __shared__ __nv_bfloat16 sm[];
    __nv_bfloat16* AH = sm;
    __nv_bfloat16* AL = sm + 128 * GSTR;
    __nv_bfloat16* BH = sm + 2 * 128 * GSTR;
    __nv_bfloat16* BL = sm + 3 * 128 * GSTR;

    int tid = threadIdx.x;
    int lane = tid & 31, wid = tid >> 5;
    int rowBase = blockIdx.x * 128;
    int colBase = blockIdx.y * 128;

#pragma unroll
    for (int it = 0; it < 8; it++) {
        int p = tid + it * 256;
        int m = p >> 4;
        int koct = p & 15;
        const float* src = &g_x2[(long)(rowBase + m) * 128 + koct * 8];
        float4 v0 = *(const float4*)src;
        float4 v1 = *(const float4*)(src + 4);
        float v[8] = {v0.x, v0.y, v0.z, v0.w, v1.x, v1.y, v1.z, v1.w};
        uint4 hi, lo;
        split8(v, hi, lo);
        *(uint4*)&AH[m * GSTR + koct * 8] = hi;
        *(uint4*)&AL[m * GSTR + koct * 8] = lo;
    }
#pragma unroll
    for (int it = 0; it < 8; it++) {
        int p = tid + it * 256;
        int n = p & 127;
        int koct = p >> 7;
        const float* W = (koct < 8) ? Wl2 : Wr2;
        int kr0 = (koct * 8) & 63;
        float v[8];
#pragma unroll
        for (int j = 0; j < 8; j++)
            v[j] = W[(long)(kr0 + j) * 2048 + colBase + n];
        uint4 hi, lo;
        split8(v, hi, lo);
        *(uint4*)&BH[n * GSTR + koct * 8] = hi;
        *(uint4*)&BL[n * GSTR + koct * 8] = lo;
    }
    __syncthreads();

    int tig = lane & 3, grp = lane >> 2;
    int wm = (wid >> 2) * 64;
    int wn = (wid & 3) * 32;

    float acc[4][4][4] = {};

#pragma unroll
    for (int ks = 0; ks < 8; ks++) {
        int kw = ks * 8 + tig;
        uint32_t aH[4][4], aL[4][4], bH[4][2], bL[4][2];
#pragma unroll
        for (int mt = 0; mt < 4; mt++) {
            const __nv_bfloat16* pH = &AH[(wm + mt * 16 + grp) * GSTR + kw * 2];
            const __nv_bfloat16* pL = &AL[(wm + mt * 16 + grp) * GSTR + kw * 2];
            aH[mt][0] = *(const uint32_t*)pH;
            aH[mt][1] = *(const uint32_t*)(pH + 8 * GSTR);
            aH[mt][2] = *(const uint32_t*)(pH + 8);
            aH[mt][3] = *(const uint32_t*)(pH + 8 * GSTR + 8);
            aL[mt][0] = *(const uint32_t*)pL;
            aL[mt][1] = *(const uint32_t*)(pL + 8 * GSTR);
            aL[mt][2] = *(const uint32_t*)(pL + 8);
            aL[mt][3] = *(const uint32_t*)(pL + 8 * GSTR + 8);
        }
#pragma unroll
        for (int nt = 0; nt < 4; nt++) {
            const __nv_bfloat16* pH = &BH[(wn + nt * 8 + grp) * GSTR + kw * 2];
            const __nv_bfloat16* pL = &BL[(wn + nt * 8 + grp) * GSTR + kw * 2];
            bH[nt][0] = *(const uint32_t*)pH;
            bH[nt][1] = *(const uint32_t*)(pH + 8);
            bL[nt][0] = *(const uint32_t*)pL;
            bL[nt][1] = *(const uint32_t*)(pL + 8);
        }
#pragma unroll
        for (int mt = 0; mt < 4; mt++)
#pragma unroll
            for (int nt = 0; nt < 4; nt++) {
                MMA16816(acc[mt][nt], aH[mt], bH[nt]);
                MMA16816(acc[mt][nt], aH[mt], bL[nt]);
                MMA16816(acc[mt][nt], aL[mt], bH[nt]);
            }
    }

#pragma unroll
    for (int mt = 0; mt < 4; mt++) {
#pragma unroll
        for (int nt = 0; nt < 4; nt++) {
            int row = rowBase + wm + mt * 16 + grp;
            int col = colBase + wn + nt * 8 + tig * 2;
            float2 bv = *(const float2*)&bl2[col];
            if (row < N_MASK) {
                float2 o = make_float2(acc[mt][nt][0] + bv.x, acc[mt][nt][1] + bv.y);
                *(float2*)&g_logits[(long)row * 2048 + col] = o;
            }
            if (row + 8 < N_MASK) {
                float2 o = make_float2(acc[mt][nt][2] + bv.x, acc[mt][nt][3] + bv.y);
                *(float2*)&g_logits[(long)(row + 8) * 2048 + col] = o;
            }
        }
    }
}

// ---------------- row-wise log_softmax --------------------------------------
__global__ void softmax_kernel(float* out) {
    __shared__ float sred[256];
    int r = blockIdx.x;
    int t = threadIdx.x;
    const float4* L = (const float4*)&g_logits[(long)r * 2048];
    float4 v0 = L[t], v1 = L[t + 256];

    float mx = fmaxf(fmaxf(fmaxf(v0.x, v0.y), fmaxf(v0.z, v0.w)),
                     fmaxf(fmaxf(v1.x, v1.y), fmaxf(v1.z, v1.w)));
    sred[t] = mx; __syncthreads();
    for (int s = 128; s > 0; s >>= 1) {
        if (t < s) sred[t] = fmaxf(sred[t], sred[t + s]);
        __syncthreads();
    }
    mx = sred[0];
    __syncthreads();

    float sum = expf(v0.x - mx) + expf(v0.y - mx) + expf(v0.z - mx) + expf(v0.w - mx)
              + expf(v1.x - mx) + expf(v1.y - mx) + expf(v1.z - mx) + expf(v1.w - mx);
    sred[t] = sum; __syncthreads();
    for (int s = 128; s > 0; s >>= 1) {
        if (t < s) sred[t] += sred[t + s];
        __syncthreads();
    }
    float shift = mx + logf(sred[0]);

    float4* O = (float4*)&out[(long)r * 2048];
    O[t]       = make_float4(v0.x - shift, v0.y - shift, v0.z - shift, v0.w - shift);
    O[t + 256] = make_float4(v1.x - shift, v1.y - shift, v1.z - shift, v1.w - shift);
}

// ---------------- launch ----------------------------------------------------
extern "C" void kernel_launch(void* const* d_in, const int* in_sizes, int n_in,
                              void* d_out, int out_size) {
    const void*  x    = d_in[0];
    const void*  edge = d_in[1];
    const void*  mask = d_in[2];
    const float* emb  = (const float*)d_in[3];
    const float* Wl1  = (const float*)d_in[4];
    const float* bl1  = (const float*)d_in[5];
    const float* Wr1  = (const float*)d_in[6];
    const float* Wl2  = (const float*)d_in[7];
    const float* bl2  = (const float*)d_in[8];
    const float* Wr2  = (const float*)d_in[9];
    float* out = (float*)d_out;

    cudaFuncSetAttribute(gemm2_mma, cudaFuncAttributeMaxDynamicSharedMemorySize, GT_SMEM);
    cudaFuncSetAttribute(dense1_mma, cudaFuncAttributeMaxDynamicSharedMemorySize, D1_SMEM);

    detect_kernel<<<1, 32>>>(edge);
    zero_kernel<<<(N_NODES + 255) / 256, 256>>>();
    hist_kernel<<<(N_EDGES / 2 + 255) / 256, 256>>>(edge);
    scan1_kernel<<<100, 256>>>();
    scan2_kernel<<<1, 128>>>();
    scan3_kernel<<<100, 256>>>();
    scatter_kernel<<<(N_EDGES / 2 + 255) / 256, 256>>>(edge);
    gather_kernel<<<(N_NODES * 16 + 255) / 256, 256>>>(x, emb);
    spmm1_kernel<<<(N_NODES * 32 + 255) / 256, 256>>>();
    dense1_mma<<<(N_NODES + 127) / 128, 256, D1_SMEM>>>(Wl1, bl1, Wr1);
    spmm2_kernel<<<(N_MASK * 32 + 255) / 256, 256>>>(mask);
    {
        dim3 grid(M_PAD / 128, 2048 / 128);
        gemm2_mma<<<grid, 256, GT_SMEM>>>(Wl2, bl2, Wr2);
    }
    softmax_kernel<<<N_MASK, 256>>>(out);
}

// round 5
// speedup vs baseline: 2.4357x; 1.0318x over previous
#include <cuda_runtime.h>
#include <cuda_bf16.h>
#include <math.h>
#include <stdint.h>

#define N_NODES 100000
#define N_EDGES 1600000
#define VOCAB   2048
#define DIM     64
#define N_MASK  10000
#define M_PAD   10112   // 79 * 128 (GEMM2 row tiles)

// ---------------- scratch (device globals: allocation-free) ----------------
__device__ int   g_is64;
__device__ int   g_deg[N_NODES];
__device__ int   g_rowptr[N_NODES + 1];
__device__ int   g_cursor[N_NODES];
__device__ int   g_col[N_EDGES];
__device__ int   g_bsum[100];
__device__ int   g_boff[100];
__device__ float g_h0[N_NODES * DIM];
__device__ float g_m1[N_NODES * DIM];
__device__ float g_h1[N_NODES * DIM];
__device__ __nv_bfloat16 g_x2h[M_PAD * 128];   // A tile bf16 hi (pad rows stay 0)
__device__ __nv_bfloat16 g_x2l[M_PAD * 128];   // A tile bf16 lo
__device__ __nv_bfloat16 g_w2h[VOCAB * 128];   // B[n][k] bf16 hi, n-major
__device__ __nv_bfloat16 g_w2l[VOCAB * 128];   // B[n][k] bf16 lo
__device__ float g_logits[N_MASK * 2048];

// ---------------- dtype detection (int32 vs int64 indices) -----------------
__global__ void detect_kernel(const void* edge) {
    const int* w = (const int*)edge;
    int lane = threadIdx.x;
    int v = w[2 * lane + 1];
    unsigned nz = __ballot_sync(0xffffffffu, v != 0);
    if (lane == 0) g_is64 = (nz == 0u) ? 1 : 0;
}

__device__ __forceinline__ int ld_idx(const void* p, long i, int is64) {
    return is64 ? (int)((const long long*)p)[i] : ((const int*)p)[i];
}

// ---------------- CSR build -------------------------------------------------
__global__ void zero_kernel() {
    int i = blockIdx.x * blockDim.x + threadIdx.x;
    if (i < N_NODES) g_deg[i] = 0;
}

// 2 edges per thread, vectorized loads
__global__ void hist_kernel(const void* edge) {
    int is64 = g_is64;
    long t = blockIdx.x * (long)blockDim.x + threadIdx.x;
    long e = t * 2;
    if (e >= N_EDGES) return;
    int d0, d1;
    if (is64) {
        longlong2 v = *(const longlong2*)((const long long*)edge + N_EDGES + e);
        d0 = (int)v.x; d1 = (int)v.y;
    } else {
        int2 v = *(const int2*)((const int*)edge + N_EDGES + e);
        d0 = v.x; d1 = v.y;
    }
    atomicAdd(&g_deg[d0], 1);
    atomicAdd(&g_deg[d1], 1);
}

// 3-pass parallel exclusive scan of g_deg -> g_rowptr (chunks of 1000)
__global__ void scan1_kernel() {   // 100 blocks x 256
    __shared__ int s[256];
    int b = blockIdx.x, t = threadIdx.x;
    int sum = 0;
    if (t < 250) {
        int o = b * 1000 + t * 4;
        sum = g_deg[o] + g_deg[o + 1] + g_deg[o + 2] + g_deg[o + 3];
    }
    s[t] = sum; __syncthreads();
    for (int off = 128; off > 0; off >>= 1) {
        if (t < off) s[t] += s[t + off];
        __syncthreads();
    }
    if (t == 0) g_bsum[b] = s[0];
}

__global__ void scan2_kernel() {   // 1 block x 128
    __shared__ int s[128];
    int t = threadIdx.x;
    int v = (t < 100) ? g_bsum[t] : 0;
    s[t] = v; __syncthreads();
    for (int off = 1; off < 128; off <<= 1) {
        int x = (t >= off) ? s[t - off] : 0;
        __syncthreads();
        s[t] += x;
        __syncthreads();
    }
    if (t < 100) g_boff[t] = s[t] - v;
    if (t == 99) g_rowptr[N_NODES] = s[99];
}

__global__ void scan3_kernel() {   // 100 blocks x 256; also seeds cursor=rowptr
    __shared__ int s[256];
    int b = blockIdx.x, t = threadIdx.x;
    int d0 = 0, d1 = 0, d2 = 0, d3 = 0, sum = 0;
    int o = b * 1000 + t * 4;
    if (t < 250) {
        d0 = g_deg[o]; d1 = g_deg[o + 1]; d2 = g_deg[o + 2]; d3 = g_deg[o + 3];
        sum = d0 + d1 + d2 + d3;
    }
    s[t] = sum; __syncthreads();
    for (int off = 1; off < 256; off <<= 1) {
        int x = (t >= off) ? s[t - off] : 0;
        __syncthreads();
        s[t] += x;
        __syncthreads();
    }
    if (t < 250) {
        int run = g_boff[b] + s[t] - sum;
        g_rowptr[o] = run;     g_cursor[o] = run;     run += d0;
        g_rowptr[o + 1] = run; g_cursor[o + 1] = run; run += d1;
        g_rowptr[o + 2] = run; g_cursor[o + 2] = run; run += d2;
        g_rowptr[o + 3] = run; g_cursor[o + 3] = run;
    }
}

__global__ void scatter_kernel(const void* edge) {
    int is64 = g_is64;
    long t = blockIdx.x * (long)blockDim.x + threadIdx.x;
    long e = t * 2;
    if (e >= N_EDGES) return;
    int s0, s1, d0, d1;
    if (is64) {
        longlong2 sv = *(const longlong2*)((const long long*)edge + e);
        longlong2 dv = *(const longlong2*)((const long long*)edge + N_EDGES + e);
        s0 = (int)sv.x; s1 = (int)sv.y; d0 = (int)dv.x; d1 = (int)dv.y;
    } else {
        int2 sv = *(const int2*)((const int*)edge + e);
        int2 dv = *(const int2*)((const int*)edge + N_EDGES + e);
        s0 = sv.x; s1 = sv.y; d0 = dv.x; d1 = dv.y;
    }
    g_col[atomicAdd(&g_cursor[d0], 1)] = s0;
    g_col[atomicAdd(&g_cursor[d1], 1)] = s1;
}

// ---------------- h0 = emb[x] ----------------------------------------------
__global__ void gather_kernel(const void* x, const float* emb) {
    int is64 = g_is64;
    int tid = blockIdx.x * blockDim.x + threadIdx.x;
    if (tid >= N_NODES * 16) return;
    int n = tid >> 4, j = tid & 15;
    int tok = ld_idx(x, n, is64);
    ((float4*)g_h0)[tid] = ((const float4*)emb)[tok * 16 + j];
}

// ---------------- SpMM mean, layer 1 (all nodes) ----------------------------
__global__ void spmm1_kernel() {
    int wid = (blockIdx.x * blockDim.x + threadIdx.x) >> 5;
    int lane = threadIdx.x & 31;
    if (wid >= N_NODES) return;
    int half = lane >> 4, l16 = lane & 15;
    int start = g_rowptr[wid], end = g_rowptr[wid + 1];
    float4 acc = make_float4(0.f, 0.f, 0.f, 0.f);
    const float4* h = (const float4*)g_h0;
#pragma unroll 2
    for (int p = start + half; p < end; p += 2) {
        int s = g_col[p];
        float4 v = h[(long)s * 16 + l16];
        acc.x += v.x; acc.y += v.y; acc.z += v.z; acc.w += v.w;
    }
    acc.x += __shfl_down_sync(0xffffffffu, acc.x, 16);
    acc.y += __shfl_down_sync(0xffffffffu, acc.y, 16);
    acc.z += __shfl_down_sync(0xffffffffu, acc.z, 16);
    acc.w += __shfl_down_sync(0xffffffffu, acc.w, 16);
    if (half == 0) {
        float inv = 1.0f / fmaxf((float)(end - start), 1.0f);
        ((float4*)g_m1)[(long)wid * 16 + l16] =
            make_float4(acc.x * inv, acc.y * inv, acc.z * inv, acc.w * inv);
    }
}

// =============== bf16 mma.sync helpers ======================================
static __device__ __forceinline__ uint32_t pack_bf2(float a, float b) {
    __nv_bfloat162 t = __floats2bfloat162_rn(a, b);
    return reinterpret_cast<uint32_t&>(t);
}
static __device__ __forceinline__ void split8(const float* v, uint4& hi, uint4& lo) {
    float r[8];
#pragma unroll
    for (int i = 0; i < 8; i++)
        r[i] = v[i] - __bfloat162float(__float2bfloat16(v[i]));
    hi = make_uint4(pack_bf2(v[0], v[1]), pack_bf2(v[2], v[3]),
                    pack_bf2(v[4], v[5]), pack_bf2(v[6], v[7]));
    lo = make_uint4(pack_bf2(r[0], r[1]), pack_bf2(r[2], r[3]),
                    pack_bf2(r[4], r[5]), pack_bf2(r[6], r[7]));
}
static __device__ __forceinline__ void split4(float4 v, uint2& hi, uint2& lo) {
    float rx = v.x - __bfloat162float(__float2bfloat16(v.x));
    float ry = v.y - __bfloat162float(__float2bfloat16(v.y));
    float rz = v.z - __bfloat162float(__float2bfloat16(v.z));
    float rw = v.w - __bfloat162float(__float2bfloat16(v.w));
    hi = make_uint2(pack_bf2(v.x, v.y), pack_bf2(v.z, v.w));
    lo = make_uint2(pack_bf2(rx, ry), pack_bf2(rz, rw));
}

#define MMA16816(d, a, b) \
    asm volatile( \
        "mma.sync.aligned.m16n8k16.row.col.f32.bf16.bf16.f32 " \
        "{%0,%1,%2,%3}, {%4,%5,%6,%7}, {%8,%9}, {%0,%1,%2,%3};" \
        : "+f"((d)[0]), "+f"((d)[1]), "+f"((d)[2]), "+f"((d)[3]) \
        : "r"((a)[0]), "r"((a)[1]), "r"((a)[2]), "r"((a)[3]), \
          "r"((b)[0]), "r"((b)[1]))

#define GSTR 136                             // bf16 per smem row (conflict-free)
#define D1_SMEM ((128 + 64) * 2 * GSTR * 2)  // 104448 B
#define GT_SMEM ((128 + 64) * 2 * GSTR * 2)  // gemm2 v2: same 104448 B

// ---------------- W2 split prep: [Wl2;Wr2] -> g_w2h/g_w2l [n][k] ------------
__global__ void w2prep_kernel(const float* __restrict__ Wl2,
                              const float* __restrict__ Wr2) {
    int p = blockIdx.x * blockDim.x + threadIdx.x;   // 32768
    int n = p & 2047, koct = p >> 11;
    const float* W = (koct < 8) ? Wl2 : Wr2;
    int kr0 = (koct * 8) & 63;
    float v[8];
#pragma unroll
    for (int j = 0; j < 8; j++)
        v[j] = W[(long)(kr0 + j) * 2048 + n];
    uint4 hi, lo;
    split8(v, hi, lo);
    *(uint4*)&g_w2h[n * 128 + koct * 8] = hi;
    *(uint4*)&g_w2l[n * 128 + koct * 8] = lo;
}

// ---------------- dense layer 1 (tensor-core bf16 split) --------------------
__global__ void __launch_bounds__(256, 2) dense1_mma(const float* __restrict__ Wl,
                                                     const float* __restrict__ bl,
                                                     const float* __restrict__ Wr) {
    extern __shared__ __nv_bfloat16 sm[];
    __nv_bfloat16* AH = sm;
    __nv_bfloat16* AL = sm + 128 * GSTR;
    __nv_bfloat16* BH = sm + 2 * 128 * GSTR;
    __nv_bfloat16* BL = sm + 2 * 128 * GSTR + 64 * GSTR;

    int tid = threadIdx.x;
    int lane = tid & 31, wid = tid >> 5;
    int rowBase = blockIdx.x * 128;

#pragma unroll
    for (int it = 0; it < 8; it++) {
        int p = tid + it * 256;
        int m = p >> 4, koct = p & 15;
        int node = rowBase + m;
        float v[8] = {0, 0, 0, 0, 0, 0, 0, 0};
        if (node < N_NODES) {
            const float* src = (koct < 8) ? &g_m1[(long)node * 64 + koct * 8]
                                          : &g_h0[(long)node * 64 + (koct - 8) * 8];
            float4 v0 = *(const float4*)src;
            float4 v1 = *(const float4*)(src + 4);
            v[0] = v0.x; v[1] = v0.y; v[2] = v0.z; v[3] = v0.w;
            v[4] = v1.x; v[5] = v1.y; v[6] = v1.z; v[7] = v1.w;
        }
        uint4 hi, lo;
        split8(v, hi, lo);
        *(uint4*)&AH[m * GSTR + koct * 8] = hi;
        *(uint4*)&AL[m * GSTR + koct * 8] = lo;
    }
#pragma unroll
    for (int it = 0; it < 4; it++) {
        int p = tid + it * 256;
        int n = p & 63, koct = p >> 6;
        const float* W = (koct < 8) ? Wl : Wr;
        int kr0 = (koct * 8) & 63;
        float v[8];
#pragma unroll
        for (int j = 0; j < 8; j++)
            v[j] = W[(long)(kr0 + j) * 64 + n];
        uint4 hi, lo;
        split8(v, hi, lo);
        *(uint4*)&BH[n * GSTR + koct * 8] = hi;
        *(uint4*)&BL[n * GSTR + koct * 8] = lo;
    }
    __syncthreads();

    int tig = lane & 3, grp = lane >> 2;
    int wm = (wid & 3) * 32;
    int wn = (wid >> 2) * 32;

    float acc[2][4][4] = {};

#pragma unroll
    for (int ks = 0; ks < 8; ks++) {
        int kw = ks * 8 + tig;
        uint32_t aH[2][4], aL[2][4], bH[4][2], bL[4][2];
#pragma unroll
        for (int mt = 0; mt < 2; mt++) {
            const __nv_bfloat16* pH = &AH[(wm + mt * 16 + grp) * GSTR + kw * 2];
            const __nv_bfloat16* pL = &AL[(wm + mt * 16 + grp) * GSTR + kw * 2];
            aH[mt][0] = *(const uint32_t*)pH;
            aH[mt][1] = *(const uint32_t*)(pH + 8 * GSTR);
            aH[mt][2] = *(const uint32_t*)(pH + 8);
            aH[mt][3] = *(const uint32_t*)(pH + 8 * GSTR + 8);
            aL[mt][0] = *(const uint32_t*)pL;
            aL[mt][1] = *(const uint32_t*)(pL + 8 * GSTR);
            aL[mt][2] = *(const uint32_t*)(pL + 8);
            aL[mt][3] = *(const uint32_t*)(pL + 8 * GSTR + 8);
        }
#pragma unroll
        for (int nt = 0; nt < 4; nt++) {
            const __nv_bfloat16* pH = &BH[(wn + nt * 8 + grp) * GSTR + kw * 2];
            const __nv_bfloat16* pL = &BL[(wn + nt * 8 + grp) * GSTR + kw * 2];
            bH[nt][0] = *(const uint32_t*)pH;
            bH[nt][1] = *(const uint32_t*)(pH + 8);
            bL[nt][0] = *(const uint32_t*)pL;
            bL[nt][1] = *(const uint32_t*)(pL + 8);
        }
#pragma unroll
        for (int mt = 0; mt < 2; mt++)
#pragma unroll
            for (int nt = 0; nt < 4; nt++) {
                MMA16816(acc[mt][nt], aH[mt], bH[nt]);
                MMA16816(acc[mt][nt], aH[mt], bL[nt]);
                MMA16816(acc[mt][nt], aL[mt], bH[nt]);
            }
    }

#pragma unroll
    for (int mt = 0; mt < 2; mt++) {
#pragma unroll
        for (int nt = 0; nt < 4; nt++) {
            int row = rowBase + wm + mt * 16 + grp;
            int col = wn + nt * 8 + tig * 2;
            float2 bv = *(const float2*)&bl[col];
            if (row < N_NODES) {
                float2 o = make_float2(fmaxf(acc[mt][nt][0] + bv.x, 0.f),
                                       fmaxf(acc[mt][nt][1] + bv.y, 0.f));
                *(float2*)&g_h1[(long)row * 64 + col] = o;
            }
            if (row + 8 < N_NODES) {
                float2 o = make_float2(fmaxf(acc[mt][nt][2] + bv.x, 0.f),
                                       fmaxf(acc[mt][nt][3] + bv.y, 0.f));
                *(float2*)&g_h1[(long)(row + 8) * 64 + col] = o;
            }
        }
    }
}

// ---------------- SpMM mean, layer 2: writes x2 as bf16 hi/lo ---------------
__global__ void spmm2_kernel(const void* mask) {
    int is64 = g_is64;
    int wid = (blockIdx.x * blockDim.x + threadIdx.x) >> 5;
    int lane = threadIdx.x & 31;
    if (wid >= N_MASK) return;
    int half = lane >> 4, l16 = lane & 15;
    int n = ld_idx(mask, wid, is64);
    int start = g_rowptr[n], end = g_rowptr[n + 1];
    float4 acc = make_float4(0.f, 0.f, 0.f, 0.f);
    const float4* h = (const float4*)g_h1;
#pragma unroll 2
    for (int p = start + half; p < end; p += 2) {
        int s = g_col[p];
        float4 v = h[(long)s * 16 + l16];
        acc.x += v.x; acc.y += v.y; acc.z += v.z; acc.w += v.w;
    }
    acc.x += __shfl_down_sync(0xffffffffu, acc.x, 16);
    acc.y += __shfl_down_sync(0xffffffffu, acc.y, 16);
    acc.z += __shfl_down_sync(0xffffffffu, acc.z, 16);
    acc.w += __shfl_down_sync(0xffffffffu, acc.w, 16);
    float4 v;
    long base;
    if (half == 0) {
        float inv = 1.0f / fmaxf((float)(end - start), 1.0f);
        v = make_float4(acc.x * inv, acc.y * inv, acc.z * inv, acc.w * inv);
        base = (long)wid * 128 + l16 * 4;
    } else {
        v = h[(long)n * 16 + l16];
        base = (long)wid * 128 + 64 + l16 * 4;
    }
    uint2 hi, lo;
    split4(v, hi, lo);
    *(uint2*)&g_x2h[base] = hi;
    *(uint2*)&g_x2l[base] = lo;
}

// ================= GEMM2: 128x64 tiles, 2 CTA/SM, copy-only staging =========
__global__ void __launch_bounds__(256, 2) gemm2_mma(const float* __restrict__ bl2) {
    extern __shared__ __nv_bfloat16 sm[];
    __nv_bfloat16* AH = sm;
    __nv_bfloat16* AL = sm + 128 * GSTR;
    __nv_bfloat16* BH = sm + 2 * 128 * GSTR;
    __nv_bfloat16* BL = sm + 2 * 128 * GSTR + 64 * GSTR;

    int tid = threadIdx.x;
    int lane = tid & 31, wid = tid >> 5;
    int rowBase = blockIdx.x * 128;
    int colBase = blockIdx.y * 64;

#pragma unroll
    for (int it = 0; it < 8; it++) {
        int p = tid + it * 256;          // 0..2047
        int m = p >> 4, koct = p & 15;
        long src = (long)(rowBase + m) * 128 + koct * 8;
        *(uint4*)&AH[m * GSTR + koct * 8] = *(const uint4*)&g_x2h[src];
        *(uint4*)&AL[m * GSTR + koct * 8] = *(const uint4*)&g_x2l[src];
    }
#pragma unroll
    for (int it = 0; it < 4; it++) {
        int p = tid + it * 256;          // 0..1023
        int n = p >> 4, koct = p & 15;
        long src = (long)(colBase + n) * 128 + koct * 8;
        *(uint4*)&BH[n * GSTR + koct * 8] = *(const uint4*)&g_w2h[src];
        *(uint4*)&BL[n * GSTR + koct * 8] = *(const uint4*)&g_w2l[src];
    }
    __syncthreads();

    int tig = lane & 3, grp = lane >> 2;
    int wm = (wid & 3) * 32;
    int wn = (wid >> 2) * 32;

    float acc[2][4][4] = {};

#pragma unroll
    for (int ks = 0; ks < 8; ks++) {
        int kw = ks * 8 + tig;
        uint32_t aH[2][4], aL[2][4], bH[4][2], bL[4][2];
#pragma unroll
        for (int mt = 0; mt < 2; mt++) {
            const __nv_bfloat16* pH = &AH[(wm + mt * 16 + grp) * GSTR + kw * 2];
            const __nv_bfloat16* pL = &AL[(wm + mt * 16 + grp) * GSTR + kw * 2];
            aH[mt][0] = *(const uint32_t*)pH;
            aH[mt][1] = *(const uint32_t*)(pH + 8 * GSTR);
            aH[mt][2] = *(const uint32_t*)(pH + 8);
            aH[mt][3] = *(const uint32_t*)(pH + 8 * GSTR + 8);
            aL[mt][0] = *(const uint32_t*)pL;
            aL[mt][1] = *(const uint32_t*)(pL + 8 * GSTR);
            aL[mt][2] = *(const uint32_t*)(pL + 8);
            aL[mt][3] = *(const uint32_t*)(pL + 8 * GSTR + 8);
        }
#pragma unroll
        for (int nt = 0; nt < 4; nt++) {
            const __nv_bfloat16* pH = &BH[(wn + nt * 8 + grp) * GSTR + kw * 2];
            const __nv_bfloat16* pL = &BL[(wn + nt * 8 + grp) * GSTR + kw * 2];
            bH[nt][0] = *(const uint32_t*)pH;
            bH[nt][1] = *(const uint32_t*)(pH + 8);
            bL[nt][0] = *(const uint32_t*)pL;
            bL[nt][1] = *(const uint32_t*)(pL + 8);
        }
#pragma unroll
        for (int mt = 0; mt < 2; mt++)
#pragma unroll
            for (int nt = 0; nt < 4; nt++) {
                MMA16816(acc[mt][nt], aH[mt], bH[nt]);
                MMA16816(acc[mt][nt], aH[mt], bL[nt]);
                MMA16816(acc[mt][nt], aL[mt], bH[nt]);
            }
    }

#pragma unroll
    for (int mt = 0; mt < 2; mt++) {
#pragma unroll
        for (int nt = 0; nt < 4; nt++) {
            int row = rowBase + wm + mt * 16 + grp;
            int col = colBase + wn + nt * 8 + tig * 2;
            float2 bv = *(const float2*)&bl2[col];
            if (row < N_MASK) {
                float2 o = make_float2(acc[mt][nt][0] + bv.x, acc[mt][nt][1] + bv.y);
                *(float2*)&g_logits[(long)row * 2048 + col] = o;
            }
            if (row + 8 < N_MASK) {
                float2 o = make_float2(acc[mt][nt][2] + bv.x, acc[mt][nt][3] + bv.y);
                *(float2*)&g_logits[(long)(row + 8) * 2048 + col] = o;
            }
        }
    }
}

// ---------------- row-wise log_softmax --------------------------------------
__global__ void softmax_kernel(float* out) {
    __shared__ float sred[256];
    int r = blockIdx.x;
    int t = threadIdx.x;
    const float4* L = (const float4*)&g_logits[(long)r * 2048];
    float4 v0 = L[t], v1 = L[t + 256];

    float mx = fmaxf(fmaxf(fmaxf(v0.x, v0.y), fmaxf(v0.z, v0.w)),
                     fmaxf(fmaxf(v1.x, v1.y), fmaxf(v1.z, v1.w)));
    sred[t] = mx; __syncthreads();
    for (int s = 128; s > 0; s >>= 1) {
        if (t < s) sred[t] = fmaxf(sred[t], sred[t + s]);
        __syncthreads();
    }
    mx = sred[0];
    __syncthreads();

    float sum = expf(v0.x - mx) + expf(v0.y - mx) + expf(v0.z - mx) + expf(v0.w - mx)
              + expf(v1.x - mx) + expf(v1.y - mx) + expf(v1.z - mx) + expf(v1.w - mx);
    sred[t] = sum; __syncthreads();
    for (int s = 128; s > 0; s >>= 1) {
        if (t < s) sred[t] += sred[t + s];
        __syncthreads();
    }
    float shift = mx + logf(sred[0]);

    float4* O = (float4*)&out[(long)r * 2048];
    O[t]       = make_float4(v0.x - shift, v0.y - shift, v0.z - shift, v0.w - shift);
    O[t + 256] = make_float4(v1.x - shift, v1.y - shift, v1.z - shift, v1.w - shift);
}

// ---------------- launch ----------------------------------------------------
extern "C" void kernel_launch(void* const* d_in, const int* in_sizes, int n_in,
                              void* d_out, int out_size) {
    const void*  x    = d_in[0];
    const void*  edge = d_in[1];
    const void*  mask = d_in[2];
    const float* emb  = (const float*)d_in[3];
    const float* Wl1  = (const float*)d_in[4];
    const float* bl1  = (const float*)d_in[5];
    const float* Wr1  = (const float*)d_in[6];
    const float* Wl2  = (const float*)d_in[7];
    const float* bl2  = (const float*)d_in[8];
    const float* Wr2  = (const float*)d_in[9];
    float* out = (float*)d_out;

    cudaFuncSetAttribute(gemm2_mma, cudaFuncAttributeMaxDynamicSharedMemorySize, GT_SMEM);
    cudaFuncSetAttribute(dense1_mma, cudaFuncAttributeMaxDynamicSharedMemorySize, D1_SMEM);

    detect_kernel<<<1, 32>>>(edge);
    zero_kernel<<<(N_NODES + 255) / 256, 256>>>();
    hist_kernel<<<(N_EDGES / 2 + 255) / 256, 256>>>(edge);
    scan1_kernel<<<100, 256>>>();
    scan2_kernel<<<1, 128>>>();
    scan3_kernel<<<100, 256>>>();
    scatter_kernel<<<(N_EDGES / 2 + 255) / 256, 256>>>(edge);
    w2prep_kernel<<<128, 256>>>(Wl2, Wr2);
    gather_kernel<<<(N_NODES * 16 + 255) / 256, 256>>>(x, emb);
    spmm1_kernel<<<(N_NODES * 32 + 255) / 256, 256>>>();
    dense1_mma<<<(N_NODES + 127) / 128, 256, D1_SMEM>>>(Wl1, bl1, Wr1);
    spmm2_kernel<<<(N_MASK * 32 + 255) / 256, 256>>>(mask);
    {
        dim3 grid(M_PAD / 128, 2048 / 64);
        gemm2_mma<<<grid, 256, GT_SMEM>>>(bl2);
    }
    softmax_kernel<<<N_MASK, 256>>>(out);
}